// round 1
// baseline (speedup 1.0000x reference)
#include <cuda_runtime.h>

// HashEmbedder: 16-level multires hash grid, F=2, IN_DIM=3, K=8 corners.
// Levels 0..5 dense (row-major), 6..15 hashed (XOR-prime, mod 524309).
// One thread per (point, level). Output row: [x0,x1,x2, L0f0,L0f1, ..., L15f1] = 35 floats.

#define T_HASH 524309ULL
// Barrett magic: ceil(2^64 / T). Exact floor-div for n < 2^38 since e*n < 2^64.
#define BARRETT_M ((0xFFFFFFFFFFFFFFFFULL / T_HASH) + 1ULL)

__device__ __forceinline__ unsigned int mod_T(unsigned long long n) {
    unsigned long long q = __umul64hi(n, BARRETT_M);
    return (unsigned int)(n - q * T_HASH);
}

// Per-level resolutions: int(16 * 1.38^i). All values >0.04 from integer
// boundaries in double arithmetic, so pow-rounding cannot flip them.
__device__ const int g_n[16] = {16,22,30,42,58,80,110,152,210,290,400,553,763,1053,1453,2005};
// ENTRIES_SIZE = float32(1.0/(n-1)) — same double->float rounding as numpy.
__device__ const float g_es[16] = {
    (float)(1.0/15.0),   (float)(1.0/21.0),   (float)(1.0/29.0),   (float)(1.0/41.0),
    (float)(1.0/57.0),   (float)(1.0/79.0),   (float)(1.0/109.0),  (float)(1.0/151.0),
    (float)(1.0/209.0),  (float)(1.0/289.0),  (float)(1.0/399.0),  (float)(1.0/552.0),
    (float)(1.0/762.0),  (float)(1.0/1052.0), (float)(1.0/1452.0), (float)(1.0/2004.0)};
// cumsum of n^3 for dense levels: 0, 16^3, +22^3, +30^3, +42^3, +58^3
__device__ const int g_base[6] = {0, 4096, 14744, 41744, 115832, 310944};

__global__ void __launch_bounds__(256)
hashenc_kernel(const float* __restrict__ xyz,
               const float* __restrict__ dense,
               const float* __restrict__ hasht,
               float* __restrict__ out,
               int npts)
{
    int idx = blockIdx.x * 256 + threadIdx.x;
    int p = idx >> 4;        // point
    if (p >= npts) return;
    int l = idx & 15;        // level

    float x0 = xyz[3 * p + 0];
    float x1 = xyz[3 * p + 1];
    float x2 = xyz[3 * p + 2];

    float* orow = out + (long long)p * 35;
    if (l == 0) {            // include_input passthrough (bounds are [0,1] -> identity)
        orow[0] = x0; orow[1] = x1; orow[2] = x2;
    }

    float es  = g_es[l];
    int   n   = g_n[l];
    int   nm1 = n - 1;

    // flt = x / entries_size  (IEEE f32 divide, matching the reference exactly)
    float f0 = __fdiv_rn(x0, es);
    float f1 = __fdiv_rn(x1, es);
    float f2 = __fdiv_rn(x2, es);

    // (int64)(flt + bit) with flt >= 0: trunc == floor, and flt+1.0f is exact.
    int i0 = (int)f0, i1 = (int)f1, i2 = (int)f2;
    int a0 = min(i0, nm1),     a1 = min(i1, nm1),     a2 = min(i2, nm1);
    int b0 = min(i0 + 1, nm1), b1 = min(i1 + 1, nm1), b2 = min(i2 + 1, nm1);

    // fractional offset from (clipped) corner 0; weights use dims 0,1 only
    float o0 = f0 - (float)a0;
    float o1 = f1 - (float)a1;
    float u0 = 1.0f - o0, u1 = 1.0f - o1;
    float w00 = u0 * u1, w01 = u0 * o1, w10 = o0 * u1, w11 = o0 * o1;

    float2 v0, v1, v2, v3, v4, v5, v6, v7;

    if (l < 6) {
        const float2* d2 = (const float2*)dense;
        int base = g_base[l];
        int s1 = n, s0 = n * n;
        int A0 = a0 * s0 + base, B0 = b0 * s0 + base;
        int A1 = a1 * s1,        B1 = b1 * s1;
        v0 = __ldg(d2 + (A0 + A1 + a2));
        v1 = __ldg(d2 + (A0 + A1 + b2));
        v2 = __ldg(d2 + (A0 + B1 + a2));
        v3 = __ldg(d2 + (A0 + B1 + b2));
        v4 = __ldg(d2 + (B0 + A1 + a2));
        v5 = __ldg(d2 + (B0 + A1 + b2));
        v6 = __ldg(d2 + (B0 + B1 + a2));
        v7 = __ldg(d2 + (B0 + B1 + b2));
    } else {
        const float2* h2 = (const float2*)hasht + (unsigned long long)(l - 6) * T_HASH;
        // ih = 1 ^ (x0*1) ^ (x1*19349663) ^ (x2*83492791), then % T  (all non-negative)
        unsigned long long A0h = 1ULL ^ (unsigned long long)(unsigned)a0;
        unsigned long long B0h = 1ULL ^ (unsigned long long)(unsigned)b0;
        unsigned long long A1h = (unsigned long long)(unsigned)a1 * 19349663ULL;
        unsigned long long B1h = (unsigned long long)(unsigned)b1 * 19349663ULL;
        unsigned long long A2h = (unsigned long long)(unsigned)a2 * 83492791ULL;
        unsigned long long B2h = (unsigned long long)(unsigned)b2 * 83492791ULL;
        v0 = __ldg(h2 + mod_T(A0h ^ A1h ^ A2h));
        v1 = __ldg(h2 + mod_T(A0h ^ A1h ^ B2h));
        v2 = __ldg(h2 + mod_T(A0h ^ B1h ^ A2h));
        v3 = __ldg(h2 + mod_T(A0h ^ B1h ^ B2h));
        v4 = __ldg(h2 + mod_T(B0h ^ A1h ^ A2h));
        v5 = __ldg(h2 + mod_T(B0h ^ A1h ^ B2h));
        v6 = __ldg(h2 + mod_T(B0h ^ B1h ^ A2h));
        v7 = __ldg(h2 + mod_T(B0h ^ B1h ^ B2h));
    }

    // corner i: dim0 bit = i>>2, dim1 bit = (i>>1)&1, dim2 bit = i&1 (weight ignores dim2)
    float rx = w00 * (v0.x + v1.x) + w01 * (v2.x + v3.x)
             + w10 * (v4.x + v5.x) + w11 * (v6.x + v7.x);
    float ry = w00 * (v0.y + v1.y) + w01 * (v2.y + v3.y)
             + w10 * (v4.y + v5.y) + w11 * (v6.y + v7.y);

    orow[3 + 2 * l] = rx;
    orow[4 + 2 * l] = ry;
}

extern "C" void kernel_launch(void* const* d_in, const int* in_sizes, int n_in,
                              void* d_out, int out_size) {
    const float* xyz   = (const float*)d_in[0];   // (2,65536,3) f32
    const float* dense = (const float*)d_in[1];   // (822944,2) f32
    const float* hasht = (const float*)d_in[2];   // (10,524309,2) f32
    float* out = (float*)d_out;                   // (2,65536,35) f32

    int npts = in_sizes[0] / 3;
    int total = npts * 16;
    int blocks = (total + 255) / 256;
    hashenc_kernel<<<blocks, 256>>>(xyz, dense, hasht, out, npts);
}